// round 2
// baseline (speedup 1.0000x reference)
#include <cuda_runtime.h>
#include <math.h>

#define BB   2
#define SS   2048
#define HIDN 2048
#define NH   16
#define NKV  4
#define GG   4
#define DD   128
#define MAXS 4096

// ---------------- scratch (no allocations allowed) ----------------
__device__ float g_h  [(size_t)BB*SS*HIDN];
__device__ float g_q  [(size_t)BB*SS*NH*DD];
__device__ float g_k  [(size_t)BB*SS*NKV*DD];
__device__ float g_v  [(size_t)BB*SS*NKV*DD];
__device__ float g_ctx[(size_t)BB*SS*NH*DD];

// ---------------- RMSNorm ----------------
__global__ void rmsnorm_kernel(const float* __restrict__ x,
                               const float* __restrict__ w,
                               float* __restrict__ h)
{
    int row = blockIdx.x;
    const float* xr = x + (size_t)row * HIDN;
    float* hr = h + (size_t)row * HIDN;
    float ss = 0.f;
    for (int i = threadIdx.x; i < HIDN; i += blockDim.x) { float v = xr[i]; ss += v * v; }
    __shared__ float sred[32];
    #pragma unroll
    for (int o = 16; o > 0; o >>= 1) ss += __shfl_xor_sync(0xffffffffu, ss, o);
    if ((threadIdx.x & 31) == 0) sred[threadIdx.x >> 5] = ss;
    __syncthreads();
    if (threadIdx.x < 32) {
        float v = (threadIdx.x < (blockDim.x >> 5)) ? sred[threadIdx.x] : 0.f;
        #pragma unroll
        for (int o = 16; o > 0; o >>= 1) v += __shfl_xor_sync(0xffffffffu, v, o);
        if (threadIdx.x == 0) sred[0] = v;
    }
    __syncthreads();
    float rstd = rsqrtf(sred[0] / (float)HIDN + 1e-6f);
    for (int i = threadIdx.x; i < HIDN; i += blockDim.x) hr[i] = xr[i] * rstd * w[i];
}

// ---------------- SGEMM: C[M,N] = A[M,K] @ B[K,N] (+bias[N]) (+Cadd[M,N]) ----------------
// BM=128, BN=128, BK=8, 256 threads, 8x8 per thread (2x2 blocks of 4x4)
template<bool HAS_BIAS, bool HAS_ADD>
__global__ void sgemm_kernel(const float* __restrict__ A, const float* __restrict__ Bm,
                             const float* __restrict__ bias, const float* __restrict__ Cadd,
                             float* __restrict__ C, int M, int N, int K)
{
    __shared__ float As[8][128];
    __shared__ float Bs[8][128];
    int tid = threadIdx.x;
    int tx = tid & 15, ty = tid >> 4;
    int rowblk = blockIdx.y * 128, colblk = blockIdx.x * 128;

    float acc[8][8];
    #pragma unroll
    for (int i = 0; i < 8; i++)
        #pragma unroll
        for (int j = 0; j < 8; j++) acc[i][j] = 0.f;

    int am = tid >> 1;            // 0..127
    int ak = (tid & 1) * 4;       // 0 or 4
    int bk = tid >> 5;            // 0..7
    int bn = (tid & 31) * 4;      // 0..124

    const float* Aptr = A + (size_t)(rowblk + am) * K + ak;
    const float* Bptr = Bm + (size_t)bk * N + colblk + bn;

    for (int kt = 0; kt < K; kt += 8) {
        float4 av = *(const float4*)(Aptr + kt);
        float4 bv = *(const float4*)(Bptr + (size_t)kt * N);
        __syncthreads();
        As[ak + 0][am] = av.x; As[ak + 1][am] = av.y;
        As[ak + 2][am] = av.z; As[ak + 3][am] = av.w;
        *(float4*)&Bs[bk][bn] = bv;
        __syncthreads();
        #pragma unroll
        for (int k = 0; k < 8; k++) {
            float a[8], b[8];
            #pragma unroll
            for (int i = 0; i < 4; i++) { a[i] = As[k][ty * 4 + i]; a[4 + i] = As[k][64 + ty * 4 + i]; }
            #pragma unroll
            for (int j = 0; j < 4; j++) { b[j] = Bs[k][tx * 4 + j]; b[4 + j] = Bs[k][64 + tx * 4 + j]; }
            #pragma unroll
            for (int i = 0; i < 8; i++)
                #pragma unroll
                for (int j = 0; j < 8; j++) acc[i][j] += a[i] * b[j];
        }
    }

    #pragma unroll
    for (int i = 0; i < 8; i++) {
        int r = rowblk + ((i < 4) ? (ty * 4 + i) : (64 + ty * 4 + (i - 4)));
        #pragma unroll
        for (int j = 0; j < 8; j++) {
            int c = colblk + ((j < 4) ? (tx * 4 + j) : (64 + tx * 4 + (j - 4)));
            float v = acc[i][j];
            if (HAS_BIAS) v += bias[c];
            if (HAS_ADD)  v += Cadd[(size_t)r * N + c];
            C[(size_t)r * N + c] = v;
        }
    }
}

// ---------------- RoPE (interleaved), in-place on g_q / g_k ----------------
__global__ void rope_kernel(const float* __restrict__ cosb, const float* __restrict__ sinb)
{
    int idx = blockIdx.x * blockDim.x + threadIdx.x;
    const int perbs = (NH + NKV) * (DD / 2);          // 1280
    const int total = BB * SS * perbs;
    if (idx >= total) return;
    int bs = idx / perbs, r = idx % perbs;
    int b = bs / SS, s = bs % SS;
    const float* cp = cosb + ((size_t)(b * SS + s)) * DD;
    const float* sp = sinb + ((size_t)(b * SS + s)) * DD;
    float* ptr; int i;
    if (r < NH * (DD / 2)) {
        int h = r / (DD / 2); i = r % (DD / 2);
        ptr = g_q + (((size_t)(b * SS + s)) * NH + h) * DD;
    } else {
        int rr = r - NH * (DD / 2);
        int h = rr / (DD / 2); i = rr % (DD / 2);
        ptr = g_k + (((size_t)(b * SS + s)) * NKV + h) * DD;
    }
    float x0 = ptr[2 * i], x1 = ptr[2 * i + 1];
    float c0 = cp[2 * i], s0 = sp[2 * i];
    float c1 = cp[2 * i + 1], s1 = sp[2 * i + 1];
    ptr[2 * i]     = x0 * c0 - x1 * s0;
    ptr[2 * i + 1] = x1 * c1 + x0 * s1;
}

// ---------------- KV cache scatter ----------------
__global__ void scatter_kernel(const int* __restrict__ pos,
                               float* __restrict__ kc, float* __restrict__ vc)
{
    int idx = blockIdx.x * blockDim.x + threadIdx.x;
    const int total = BB * SS * NKV * DD;
    if (idx >= total) return;
    int d = idx % DD; int t = idx / DD;
    int kv = t % NKV; t /= NKV;
    int s = t % SS; int b = t / SS;
    int p = pos[s];
    size_t dst = (((size_t)b * MAXS + p) * NKV + kv) * DD + d;
    kc[dst] = g_k[idx];
    vc[dst] = g_v[idx];
}

// ---------------- Flash attention (fp32, BM=BN=64, D=128) ----------------
#define QSTR 129
#define PSTR 65
#define ATT_SMEM_FLOATS (64*QSTR*2 + 64*PSTR + 64*16*2)

__global__ void attn_kernel()
{
    extern __shared__ float sm[];
    float* Qs   = sm;                    // [64][129]
    float* Ks   = Qs + 64 * QSTR;        // [64][129] K tile, then reused for V tile
    float* Ps   = Ks + 64 * QSTR;        // [64][65]
    float* redA = Ps + 64 * PSTR;        // [64][16]
    float* redB = redA + 64 * 16;        // [64][16]

    int qt = blockIdx.x, bh = blockIdx.y;
    int b = bh >> 4, h = bh & 15, kvh = h >> 2;
    int tid = threadIdx.x, tr = tid >> 4, tc = tid & 15;
    const float scale = 0.08838834764831845f;   // 1/sqrt(128)

    // load Q tile (scaled)
    #pragma unroll
    for (int rep = 0; rep < 8; rep++) {
        int lin = rep * 256 + tid;                // 2048 float4 units
        int m = lin >> 5, d4 = (lin & 31) * 4;
        int s = qt * 64 + m;
        float4 v = *(const float4*)(g_q + (((size_t)(b * SS + s)) * NH + h) * DD + d4);
        Qs[m * QSTR + d4 + 0] = v.x * scale;
        Qs[m * QSTR + d4 + 1] = v.y * scale;
        Qs[m * QSTR + d4 + 2] = v.z * scale;
        Qs[m * QSTR + d4 + 3] = v.w * scale;
    }

    float O[4][8];
    #pragma unroll
    for (int i = 0; i < 4; i++)
        #pragma unroll
        for (int j = 0; j < 8; j++) O[i][j] = 0.f;
    float mi[4] = {-1e30f, -1e30f, -1e30f, -1e30f};
    float li[4] = {0.f, 0.f, 0.f, 0.f};
    int r0 = tr * 4, c0 = tc * 4;

    for (int kt = 0; kt <= qt; kt++) {
        __syncthreads();   // protect prev-iter V reads before overwriting Ks
        // load K tile
        #pragma unroll
        for (int rep = 0; rep < 8; rep++) {
            int lin = rep * 256 + tid;
            int m = lin >> 5, d4 = (lin & 31) * 4;
            int s = kt * 64 + m;
            float4 v = *(const float4*)(g_k + (((size_t)(b * SS + s)) * NKV + kvh) * DD + d4);
            Ks[m * QSTR + d4 + 0] = v.x;
            Ks[m * QSTR + d4 + 1] = v.y;
            Ks[m * QSTR + d4 + 2] = v.z;
            Ks[m * QSTR + d4 + 3] = v.w;
        }
        __syncthreads();

        float sc[4][4];
        #pragma unroll
        for (int i = 0; i < 4; i++)
            #pragma unroll
            for (int j = 0; j < 4; j++) sc[i][j] = 0.f;
        #pragma unroll 8
        for (int k = 0; k < DD; k++) {
            float qv[4], kvv[4];
            #pragma unroll
            for (int i = 0; i < 4; i++) qv[i] = Qs[(r0 + i) * QSTR + k];
            #pragma unroll
            for (int j = 0; j < 4; j++) kvv[j] = Ks[(c0 + j) * QSTR + k];
            #pragma unroll
            for (int i = 0; i < 4; i++)
                #pragma unroll
                for (int j = 0; j < 4; j++) sc[i][j] += qv[i] * kvv[j];
        }
        if (kt == qt) {
            #pragma unroll
            for (int i = 0; i < 4; i++)
                #pragma unroll
                for (int j = 0; j < 4; j++)
                    if (c0 + j > r0 + i) sc[i][j] = -1e30f;
        }

        // row-max partials
        #pragma unroll
        for (int i = 0; i < 4; i++) {
            float pm = fmaxf(fmaxf(sc[i][0], sc[i][1]), fmaxf(sc[i][2], sc[i][3]));
            redA[(r0 + i) * 16 + tc] = pm;
        }
        __syncthreads();   // also guarantees everyone is done reading Ks (K)

        float alpha[4];
        #pragma unroll
        for (int i = 0; i < 4; i++) {
            float tm = mi[i];
            #pragma unroll
            for (int t = 0; t < 16; t++) tm = fmaxf(tm, redA[(r0 + i) * 16 + t]);
            alpha[i] = __expf(mi[i] - tm);
            mi[i] = tm;
        }
        float psum[4];
        #pragma unroll
        for (int i = 0; i < 4; i++) {
            float s = 0.f;
            #pragma unroll
            for (int j = 0; j < 4; j++) {
                float p = __expf(sc[i][j] - mi[i]);
                Ps[(r0 + i) * PSTR + c0 + j] = p;
                s += p;
            }
            psum[i] = s;
        }
        // load V tile into Ks (K reads are done — sync above)
        #pragma unroll
        for (int rep = 0; rep < 8; rep++) {
            int lin = rep * 256 + tid;
            int m = lin >> 5, d4 = (lin & 31) * 4;
            int s = kt * 64 + m;
            float4 v = *(const float4*)(g_v + (((size_t)(b * SS + s)) * NKV + kvh) * DD + d4);
            Ks[m * QSTR + d4 + 0] = v.x;
            Ks[m * QSTR + d4 + 1] = v.y;
            Ks[m * QSTR + d4 + 2] = v.z;
            Ks[m * QSTR + d4 + 3] = v.w;
        }
        #pragma unroll
        for (int i = 0; i < 4; i++) redB[(r0 + i) * 16 + tc] = psum[i];
        __syncthreads();

        #pragma unroll
        for (int i = 0; i < 4; i++) {
            float s = 0.f;
            #pragma unroll
            for (int t = 0; t < 16; t++) s += redB[(r0 + i) * 16 + t];
            li[i] = li[i] * alpha[i] + s;
            #pragma unroll
            for (int j = 0; j < 8; j++) O[i][j] *= alpha[i];
        }
        // PV: O cols = {tc*4+j} and {64+tc*4+j}
        #pragma unroll 4
        for (int n = 0; n < 64; n++) {
            float pv[4];
            #pragma unroll
            for (int i = 0; i < 4; i++) pv[i] = Ps[(r0 + i) * PSTR + n];
            float vv[8];
            #pragma unroll
            for (int j = 0; j < 4; j++) {
                vv[j]     = Ks[n * QSTR + c0 + j];
                vv[4 + j] = Ks[n * QSTR + 64 + c0 + j];
            }
            #pragma unroll
            for (int i = 0; i < 4; i++)
                #pragma unroll
                for (int j = 0; j < 8; j++) O[i][j] += pv[i] * vv[j];
        }
    }

    // write ctx
    #pragma unroll
    for (int i = 0; i < 4; i++) {
        int s = qt * 64 + r0 + i;
        float inv = 1.f / li[i];
        float* op = g_ctx + (((size_t)(b * SS + s)) * NH + h) * DD;
        #pragma unroll
        for (int j = 0; j < 4; j++) {
            op[c0 + j]      = O[i][j] * inv;
            op[64 + c0 + j] = O[i][4 + j] * inv;
        }
    }
}

// ---------------- launch ----------------
extern "C" void kernel_launch(void* const* d_in, const int* in_sizes, int n_in,
                              void* d_out, int out_size)
{
    const float* hidden = (const float*)d_in[0];
    const float* lnw    = (const float*)d_in[1];
    const float* Wq     = (const float*)d_in[2];
    const float* bq     = (const float*)d_in[3];
    const float* Wk     = (const float*)d_in[4];
    const float* bk     = (const float*)d_in[5];
    const float* Wv     = (const float*)d_in[6];
    const float* bv     = (const float*)d_in[7];
    const float* Wo     = (const float*)d_in[8];
    const float* cosb   = (const float*)d_in[9];
    const float* sinb   = (const float*)d_in[10];
    const float* kc_in  = (const float*)d_in[11];
    const float* vc_in  = (const float*)d_in[12];
    const int*   pos    = (const int*)d_in[13];

    float* out    = (float*)d_out;
    float* kc_out = out + (size_t)BB * SS * HIDN;
    float* vc_out = kc_out + (size_t)BB * MAXS * NKV * DD;

    float *ph, *pq, *pk, *pv, *pctx;
    cudaGetSymbolAddress((void**)&ph,   g_h);
    cudaGetSymbolAddress((void**)&pq,   g_q);
    cudaGetSymbolAddress((void**)&pk,   g_k);
    cudaGetSymbolAddress((void**)&pv,   g_v);
    cudaGetSymbolAddress((void**)&pctx, g_ctx);

    const int M = BB * SS;   // 4096

    // 1. RMSNorm
    rmsnorm_kernel<<<M, 256>>>(hidden, lnw, ph);

    // 2. QKV projections
    sgemm_kernel<true, false><<<dim3(16, 32), 256>>>(ph, Wq, bq, nullptr, pq, M, NH * DD, HIDN);
    sgemm_kernel<true, false><<<dim3(4, 32),  256>>>(ph, Wk, bk, nullptr, pk, M, NKV * DD, HIDN);
    sgemm_kernel<true, false><<<dim3(4, 32),  256>>>(ph, Wv, bv, nullptr, pv, M, NKV * DD, HIDN);

    // 3. RoPE on q and k
    {
        int total = BB * SS * (NH + NKV) * (DD / 2);
        rope_kernel<<<(total + 255) / 256, 256>>>(cosb, sinb);
    }

    // 4. KV cache: copy input caches, then scatter new rows
    cudaMemcpyAsync(kc_out, kc_in, (size_t)BB * MAXS * NKV * DD * sizeof(float),
                    cudaMemcpyDeviceToDevice);
    cudaMemcpyAsync(vc_out, vc_in, (size_t)BB * MAXS * NKV * DD * sizeof(float),
                    cudaMemcpyDeviceToDevice);
    {
        int total = BB * SS * NKV * DD;
        scatter_kernel<<<(total + 255) / 256, 256>>>(pos, kc_out, vc_out);
    }

    // 5. Attention
    {
        int smem = ATT_SMEM_FLOATS * (int)sizeof(float);   // ~90.9 KB
        cudaFuncSetAttribute(attn_kernel, cudaFuncAttributeMaxDynamicSharedMemorySize, smem);
        attn_kernel<<<dim3(SS / 64, BB * NH), 256, smem>>>();
    }

    // 6. Output projection + residual
    sgemm_kernel<false, true><<<dim3(16, 32), 256>>>(pctx, Wo, nullptr, hidden, out, M, HIDN, HIDN);
}

// round 6
// speedup vs baseline: 1.5990x; 1.5990x over previous
#include <cuda_runtime.h>
#include <cuda_bf16.h>
#include <math.h>
#include <stdint.h>

#define BB   2
#define SS   2048
#define HIDN 2048
#define NH   16
#define NKV  4
#define DD   128
#define MAXS 4096
#define GEMM_K 2048

// ---------------- scratch (no allocations allowed) ----------------
__device__ float g_q  [(size_t)BB*SS*NH*DD];
__device__ float g_k  [(size_t)BB*SS*NKV*DD];
__device__ float g_v  [(size_t)BB*SS*NKV*DD];
__device__ float g_ctx[(size_t)BB*SS*NH*DD];

__device__ __nv_bfloat16 g_ahi[(size_t)BB*SS*GEMM_K];
__device__ __nv_bfloat16 g_alo[(size_t)BB*SS*GEMM_K];
__device__ __nv_bfloat16 g_wqkv_hi[(size_t)3072*GEMM_K];
__device__ __nv_bfloat16 g_wqkv_lo[(size_t)3072*GEMM_K];
__device__ __nv_bfloat16 g_wo_hi[(size_t)2048*GEMM_K];
__device__ __nv_bfloat16 g_wo_lo[(size_t)2048*GEMM_K];

// ---------------- helpers ----------------
__device__ __forceinline__ uint32_t smem_u32(const void* p) {
    uint32_t a;
    asm("{ .reg .u64 t; cvta.to.shared.u64 t, %1; cvt.u32.u64 %0, t; }" : "=r"(a) : "l"(p));
    return a;
}
__device__ __forceinline__ void cp16(uint32_t dst, const void* src) {
    asm volatile("cp.async.cg.shared.global [%0], [%1], 16;" :: "r"(dst), "l"(src));
}
#define CP_COMMIT() asm volatile("cp.async.commit_group;" ::: "memory")
#define CP_WAIT(n)  asm volatile("cp.async.wait_group %0;" :: "n"(n) : "memory")

__device__ __forceinline__ uint32_t lds32(uint32_t addr) {
    uint32_t v;
    asm volatile("ld.shared.b32 %0, [%1];" : "=r"(v) : "r"(addr));
    return v;
}
__device__ __forceinline__ void mma16816(float* d, const uint32_t* a, const uint32_t* b) {
    asm volatile(
        "mma.sync.aligned.m16n8k16.row.col.f32.bf16.bf16.f32 "
        "{%0,%1,%2,%3}, {%4,%5,%6,%7}, {%8,%9}, {%0,%1,%2,%3};"
        : "+f"(d[0]), "+f"(d[1]), "+f"(d[2]), "+f"(d[3])
        : "r"(a[0]), "r"(a[1]), "r"(a[2]), "r"(a[3]), "r"(b[0]), "r"(b[1]));
}

// ---------------- RMSNorm fused with bf16 hi/lo split ----------------
__global__ void rmsnorm_split_kernel(const float* __restrict__ x,
                                     const float* __restrict__ w,
                                     __nv_bfloat16* __restrict__ hi,
                                     __nv_bfloat16* __restrict__ lo)
{
    int row = blockIdx.x;
    const float* xr = x + (size_t)row * HIDN;
    float ss = 0.f;
    for (int i = threadIdx.x; i < HIDN; i += blockDim.x) { float v = xr[i]; ss += v * v; }
    __shared__ float sred[32];
    #pragma unroll
    for (int o = 16; o > 0; o >>= 1) ss += __shfl_xor_sync(0xffffffffu, ss, o);
    if ((threadIdx.x & 31) == 0) sred[threadIdx.x >> 5] = ss;
    __syncthreads();
    if (threadIdx.x < 32) {
        float v = (threadIdx.x < (blockDim.x >> 5)) ? sred[threadIdx.x] : 0.f;
        #pragma unroll
        for (int o = 16; o > 0; o >>= 1) v += __shfl_xor_sync(0xffffffffu, v, o);
        if (threadIdx.x == 0) sred[0] = v;
    }
    __syncthreads();
    float rstd = rsqrtf(sred[0] / (float)HIDN + 1e-6f);
    for (int i = threadIdx.x; i < HIDN; i += blockDim.x) {
        float y = xr[i] * rstd * w[i];
        __nv_bfloat16 h = __float2bfloat16(y);
        size_t o = (size_t)row * HIDN + i;
        hi[o] = h;
        lo[o] = __float2bfloat16(y - __bfloat162float(h));
    }
}

// ---------------- fp32 elementwise split ----------------
__global__ void split_kernel(const float* __restrict__ src,
                             __nv_bfloat16* __restrict__ hi,
                             __nv_bfloat16* __restrict__ lo, int n)
{
    int i = blockIdx.x * blockDim.x + threadIdx.x;
    if (i >= n) return;
    float v = src[i];
    __nv_bfloat16 h = __float2bfloat16(v);
    hi[i] = h;
    lo[i] = __float2bfloat16(v - __bfloat162float(h));
}

// ---------------- weight transpose + split: W[K,Nsrc] -> Wt[n0+n][K] bf16 hi/lo ----------------
__global__ void transpose_split_kernel(const float* __restrict__ W, int Nsrc, int n0,
                                       __nv_bfloat16* __restrict__ hi,
                                       __nv_bfloat16* __restrict__ lo)
{
    __shared__ float t[32][33];
    int k0 = blockIdx.x * 32, nloc0 = blockIdx.y * 32;
    int tx = threadIdx.x & 31, ty = threadIdx.x >> 5;   // 32 x 8
    #pragma unroll
    for (int i = 0; i < 4; i++) {
        int k = k0 + ty + i * 8;
        t[ty + i * 8][tx] = W[(size_t)k * Nsrc + nloc0 + tx];
    }
    __syncthreads();
    #pragma unroll
    for (int i = 0; i < 4; i++) {
        int n = nloc0 + ty + i * 8;
        int k = k0 + tx;
        float v = t[tx][ty + i * 8];
        __nv_bfloat16 h = __float2bfloat16(v);
        size_t o = (size_t)(n0 + n) * GEMM_K + k;
        hi[o] = h;
        lo[o] = __float2bfloat16(v - __bfloat162float(h));
    }
}

// ---------------- HMMA GEMM: C = A @ B^T, bf16x3 split, fp32 accum ----------------
// CTA tile 128x128, BK=32 bf16. 8 warps = 2x4 of 64x32 warp tiles.
// SMEM tiles: row stride 40 bf16 (80B) -> conflict-free fragment LDS.
#define ASTR 40
#define TILE_BYTES (128*ASTR*2)      // 10240
#define STAGE_BYTES (4*TILE_BYTES)   // 40960  (A_hi, A_lo, B_hi, B_lo)
#define GSMEM (2*STAGE_BYTES)        // 81920

template<int MODE>   // 0 = QKV (bias + route), 1 = Wo (residual)
__global__ void __launch_bounds__(256) mma_gemm_kernel(
    const __nv_bfloat16* __restrict__ a_hi, const __nv_bfloat16* __restrict__ a_lo,
    const __nv_bfloat16* __restrict__ b_hi, const __nv_bfloat16* __restrict__ b_lo,
    const float* __restrict__ bq, const float* __restrict__ bk, const float* __restrict__ bv,
    const float* __restrict__ resid,
    float* __restrict__ outq, float* __restrict__ outk, float* __restrict__ outv)
{
    extern __shared__ char smem[];
    uint32_t sb = smem_u32(smem);
    const int tid = threadIdx.x, lane = tid & 31, wid = tid >> 5;
    const int wm = wid >> 2, wn = wid & 3;
    const int g = lane >> 2, c = lane & 3;
    const int rowblk = blockIdx.y * 128, colblk = blockIdx.x * 128;

    // per-thread cp.async plan: 8 x 16B, tile = rep>>1
    const __nv_bfloat16* gsrc[8];
    uint32_t soff[8];
    {
        const __nv_bfloat16* srcs[4] = { a_hi, a_lo, b_hi, b_lo };
        #pragma unroll
        for (int rep = 0; rep < 8; rep++) {
            int lin = rep * 256 + tid;
            int tile = rep >> 1;
            int w = lin & 511;
            int row = w >> 2, sec = w & 3;
            int grow = (tile < 2) ? (rowblk + row) : (colblk + row);
            gsrc[rep] = srcs[tile] + (size_t)grow * GEMM_K + sec * 8;
            soff[rep] = (uint32_t)(tile * TILE_BYTES + row * (ASTR * 2) + sec * 16);
        }
    }

    float acc[4][4][4];
    #pragma unroll
    for (int mt = 0; mt < 4; mt++)
        #pragma unroll
        for (int nt = 0; nt < 4; nt++)
            #pragma unroll
            for (int r = 0; r < 4; r++) acc[mt][nt][r] = 0.f;

    // prologue: chunk 0 -> stage 0
    #pragma unroll
    for (int rep = 0; rep < 8; rep++) cp16(sb + soff[rep], gsrc[rep]);
    CP_COMMIT();

    const int NCH = GEMM_K / 32;   // 64
    for (int kc = 0; kc < NCH; kc++) {
        if (kc + 1 < NCH) {
            uint32_t stb = sb + (uint32_t)(((kc + 1) & 1) * STAGE_BYTES);
            #pragma unroll
            for (int rep = 0; rep < 8; rep++)
                cp16(stb + soff[rep], gsrc[rep] + (kc + 1) * 32);
            CP_COMMIT();
            CP_WAIT(1);
        } else {
            CP_WAIT(0);
        }
        __syncthreads();

        uint32_t base = sb + (uint32_t)((kc & 1) * STAGE_BYTES);
        #pragma unroll
        for (int ks = 0; ks < 2; ks++) {
            uint32_t afrag[2][4][4], bfrag[2][4][2];
            int akb = (ks * 16 + 2 * c) * 2;   // byte offset of k within row
            #pragma unroll
            for (int p = 0; p < 2; p++) {
                uint32_t tb = base + (uint32_t)(p * TILE_BYTES);
                #pragma unroll
                for (int mt = 0; mt < 4; mt++) {
                    uint32_t ad = tb + (uint32_t)((wm * 64 + mt * 16 + g) * (ASTR * 2) + akb);
                    afrag[p][mt][0] = lds32(ad);
                    afrag[p][mt][1] = lds32(ad + 8 * ASTR * 2);
                    afrag[p][mt][2] = lds32(ad + 16);
                    afrag[p][mt][3] = lds32(ad + 8 * ASTR * 2 + 16);
                }
            }
            #pragma unroll
            for (int p = 0; p < 2; p++) {
                uint32_t tb = base + (uint32_t)((2 + p) * TILE_BYTES);
                #pragma unroll
                for (int nt = 0; nt < 4; nt++) {
                    uint32_t bd = tb + (uint32_t)((wn * 32 + nt * 8 + g) * (ASTR * 2) + akb);
                    bfrag[p][nt][0] = lds32(bd);
                    bfrag[p][nt][1] = lds32(bd + 16);
                }
            }
            // hi*hi, hi*lo, lo*hi
            #pragma unroll
            for (int mt = 0; mt < 4; mt++)
                #pragma unroll
                for (int nt = 0; nt < 4; nt++) mma16816(acc[mt][nt], afrag[0][mt], bfrag[0][nt]);
            #pragma unroll
            for (int mt = 0; mt < 4; mt++)
                #pragma unroll
                for (int nt = 0; nt < 4; nt++) mma16816(acc[mt][nt], afrag[0][mt], bfrag[1][nt]);
            #pragma unroll
            for (int mt = 0; mt < 4; mt++)
                #pragma unroll
                for (int nt = 0; nt < 4; nt++) mma16816(acc[mt][nt], afrag[1][mt], bfrag[0][nt]);
        }
        __syncthreads();
    }

    // epilogue
    float* dst; const float* bias = nullptr; int ncols; int cb0;
    if (MODE == 0) {
        if (colblk < 2048)      { dst = outq; ncols = 2048; cb0 = colblk;        bias = bq + cb0; }
        else if (colblk < 2560) { dst = outk; ncols = 512;  cb0 = colblk - 2048; bias = bk + cb0; }
        else                    { dst = outv; ncols = 512;  cb0 = colblk - 2560; bias = bv + cb0; }
    } else { dst = outq; ncols = 2048; cb0 = colblk; }

    #pragma unroll
    for (int mt = 0; mt < 4; mt++) {
        #pragma unroll
        for (int nt = 0; nt < 4; nt++) {
            int r0 = rowblk + wm * 64 + mt * 16 + g;
            int cl = wn * 32 + nt * 8 + 2 * c;             // local col within 128
            #pragma unroll
            for (int half = 0; half < 2; half++) {
                int r = r0 + half * 8;
                float v0 = acc[mt][nt][half * 2 + 0];
                float v1 = acc[mt][nt][half * 2 + 1];
                if (MODE == 0) { v0 += bias[cl]; v1 += bias[cl + 1]; }
                else {
                    const float* res = resid + (size_t)r * 2048 + cb0 + cl;
                    v0 += res[0]; v1 += res[1];
                }
                float2* o = (float2*)(dst + (size_t)r * ncols + cb0 + cl);
                *o = make_float2(v0, v1);
            }
        }
    }
}

// ---------------- RoPE (interleaved), in-place on g_q / g_k ----------------
__global__ void rope_kernel(const float* __restrict__ cosb, const float* __restrict__ sinb)
{
    int idx = blockIdx.x * blockDim.x + threadIdx.x;
    const int perbs = (NH + NKV) * (DD / 2);          // 1280
    const int total = BB * SS * perbs;
    if (idx >= total) return;
    int bs = idx / perbs, r = idx % perbs;
    int b = bs / SS, s = bs % SS;
    const float* cp = cosb + ((size_t)(b * SS + s)) * DD;
    const float* sp = sinb + ((size_t)(b * SS + s)) * DD;
    float* ptr; int i;
    if (r < NH * (DD / 2)) {
        int h = r / (DD / 2); i = r % (DD / 2);
        ptr = g_q + (((size_t)(b * SS + s)) * NH + h) * DD;
    } else {
        int rr = r - NH * (DD / 2);
        int h = rr / (DD / 2); i = rr % (DD / 2);
        ptr = g_k + (((size_t)(b * SS + s)) * NKV + h) * DD;
    }
    float x0 = ptr[2 * i], x1 = ptr[2 * i + 1];
    float c0 = cp[2 * i], s0 = sp[2 * i];
    float c1 = cp[2 * i + 1], s1 = sp[2 * i + 1];
    ptr[2 * i]     = x0 * c0 - x1 * s0;
    ptr[2 * i + 1] = x1 * c1 + x0 * s1;
}

// ---------------- KV cache scatter ----------------
__global__ void scatter_kernel(const int* __restrict__ pos,
                               float* __restrict__ kc, float* __restrict__ vc)
{
    int idx = blockIdx.x * blockDim.x + threadIdx.x;
    const int total = BB * SS * NKV * DD;
    if (idx >= total) return;
    int d = idx % DD; int t = idx / DD;
    int kv = t % NKV; t /= NKV;
    int s = t % SS; int b = t / SS;
    int p = pos[s];
    size_t dst = (((size_t)b * MAXS + p) * NKV + kv) * DD + d;
    kc[dst] = g_k[idx];
    vc[dst] = g_v[idx];
}

// ---------------- Flash attention (fp32, BM=BN=64, D=128) ----------------
#define QSTR 129
#define PSTR 65
#define ATT_SMEM_FLOATS (64*QSTR*2 + 64*PSTR + 64*16*2)

__global__ void attn_kernel()
{
    extern __shared__ float sm[];
    float* Qs   = sm;
    float* Ks   = Qs + 64 * QSTR;
    float* Ps   = Ks + 64 * QSTR;
    float* redA = Ps + 64 * PSTR;
    float* redB = redA + 64 * 16;

    int qt = blockIdx.x, bh = blockIdx.y;
    int b = bh >> 4, h = bh & 15, kvh = h >> 2;
    int tid = threadIdx.x, tr = tid >> 4, tc = tid & 15;
    const float scale = 0.08838834764831845f;

    #pragma unroll
    for (int rep = 0; rep < 8; rep++) {
        int lin = rep * 256 + tid;
        int m = lin >> 5, d4 = (lin & 31) * 4;
        int s = qt * 64 + m;
        float4 v = *(const float4*)(g_q + (((size_t)(b * SS + s)) * NH + h) * DD + d4);
        Qs[m * QSTR + d4 + 0] = v.x * scale;
        Qs[m * QSTR + d4 + 1] = v.y * scale;
        Qs[m * QSTR + d4 + 2] = v.z * scale;
        Qs[m * QSTR + d4 + 3] = v.w * scale;
    }

    float O[4][8];
    #pragma unroll
    for (int i = 0; i < 4; i++)
        #pragma unroll
        for (int j = 0; j < 8; j++) O[i][j] = 0.f;
    float mi[4] = {-1e30f, -1e30f, -1e30f, -1e30f};
    float li[4] = {0.f, 0.f, 0.f, 0.f};
    int r0 = tr * 4, c0 = tc * 4;

    for (int kt = 0; kt <= qt; kt++) {
        __syncthreads();
        #pragma unroll
        for (int rep = 0; rep < 8; rep++) {
            int lin = rep * 256 + tid;
            int m = lin >> 5, d4 = (lin & 31) * 4;
            int s = kt * 64 + m;
            float4 v = *(const float4*)(g_k + (((size_t)(b * SS + s)) * NKV + kvh) * DD + d4);
            Ks[m * QSTR + d4 + 0] = v.x;
            Ks[m * QSTR + d4 + 1] = v.y;
            Ks[m * QSTR + d4 + 2] = v.z;
            Ks[m * QSTR + d4 + 3] = v.w;
        }
        __syncthreads();

        float sc[4][4];
        #pragma unroll
        for (int i = 0; i < 4; i++)
            #pragma unroll
            for (int j = 0; j < 4; j++) sc[i][j] = 0.f;
        #pragma unroll 8
        for (int k = 0; k < DD; k++) {
            float qv[4], kvv[4];
            #pragma unroll
            for (int i = 0; i < 4; i++) qv[i] = Qs[(r0 + i) * QSTR + k];
            #pragma unroll
            for (int j = 0; j < 4; j++) kvv[j] = Ks[(c0 + j) * QSTR + k];
            #pragma unroll
            for (int i = 0; i < 4; i++)
                #pragma unroll
                for (int j = 0; j < 4; j++) sc[i][j] += qv[i] * kvv[j];
        }
        if (kt == qt) {
            #pragma unroll
            for (int i = 0; i < 4; i++)
                #pragma unroll
                for (int j = 0; j < 4; j++)
                    if (c0 + j > r0 + i) sc[i][j] = -1e30f;
        }

        #pragma unroll
        for (int i = 0; i < 4; i++) {
            float pm = fmaxf(fmaxf(sc[i][0], sc[i][1]), fmaxf(sc[i][2], sc[i][3]));
            redA[(r0 + i) * 16 + tc] = pm;
        }
        __syncthreads();

        float alpha[4];
        #pragma unroll
        for (int i = 0; i < 4; i++) {
            float tm = mi[i];
            #pragma unroll
            for (int t = 0; t < 16; t++) tm = fmaxf(tm, redA[(r0 + i) * 16 + t]);
            alpha[i] = __expf(mi[i] - tm);
            mi[i] = tm;
        }
        float psum[4];
        #pragma unroll
        for (int i = 0; i < 4; i++) {
            float s = 0.f;
            #pragma unroll
            for (int j = 0; j < 4; j++) {
                float p = __expf(sc[i][j] - mi[i]);
                Ps[(r0 + i) * PSTR + c0 + j] = p;
                s += p;
            }
            psum[i] = s;
        }
        #pragma unroll
        for (int rep = 0; rep < 8; rep++) {
            int lin = rep * 256 + tid;
            int m = lin >> 5, d4 = (lin & 31) * 4;
            int s = kt * 64 + m;
            float4 v = *(const float4*)(g_v + (((size_t)(b * SS + s)) * NKV + kvh) * DD + d4);
            Ks[m * QSTR + d4 + 0] = v.x;
            Ks[m * QSTR + d4 + 1] = v.y;
            Ks[m * QSTR + d4 + 2] = v.z;
            Ks[m * QSTR + d4 + 3] = v.w;
        }
        #pragma unroll
        for (int i = 0; i < 4; i++) redB[(r0 + i) * 16 + tc] = psum[i];
        __syncthreads();

        #pragma unroll
        for (int i = 0; i < 4; i++) {
            float s = 0.f;
            #pragma unroll
            for (int t = 0; t < 16; t++) s += redB[(r0 + i) * 16 + t];
            li[i] = li[i] * alpha[i] + s;
            #pragma unroll
            for (int j = 0; j < 8; j++) O[i][j] *= alpha[i];
        }
        #pragma unroll 4
        for (int n = 0; n < 64; n++) {
            float pv[4];
            #pragma unroll
            for (int i = 0; i < 4; i++) pv[i] = Ps[(r0 + i) * PSTR + n];
            float vv[8];
            #pragma unroll
            for (int j = 0; j < 4; j++) {
                vv[j]     = Ks[n * QSTR + c0 + j];
                vv[4 + j] = Ks[n * QSTR + 64 + c0 + j];
            }
            #pragma unroll
            for (int i = 0; i < 4; i++)
                #pragma unroll
                for (int j = 0; j < 8; j++) O[i][j] += pv[i] * vv[j];
        }
    }

    #pragma unroll
    for (int i = 0; i < 4; i++) {
        int s = qt * 64 + r0 + i;
        float inv = 1.f / li[i];
        float* op = g_ctx + (((size_t)(b * SS + s)) * NH + h) * DD;
        #pragma unroll
        for (int j = 0; j < 4; j++) {
            op[c0 + j]      = O[i][j] * inv;
            op[64 + c0 + j] = O[i][4 + j] * inv;
        }
    }
}

// ---------------- launch ----------------
extern "C" void kernel_launch(void* const* d_in, const int* in_sizes, int n_in,
                              void* d_out, int out_size)
{
    const float* hidden = (const float*)d_in[0];
    const float* lnw    = (const float*)d_in[1];
    const float* Wq     = (const float*)d_in[2];
    const float* bq     = (const float*)d_in[3];
    const float* Wk     = (const float*)d_in[4];
    const float* bk     = (const float*)d_in[5];
    const float* Wv     = (const float*)d_in[6];
    const float* bv     = (const float*)d_in[7];
    const float* Wo     = (const float*)d_in[8];
    const float* cosb   = (const float*)d_in[9];
    const float* sinb   = (const float*)d_in[10];
    const float* kc_in  = (const float*)d_in[11];
    const float* vc_in  = (const float*)d_in[12];
    const int*   pos    = (const int*)d_in[13];

    float* out    = (float*)d_out;
    float* kc_out = out + (size_t)BB * SS * HIDN;
    float* vc_out = kc_out + (size_t)BB * MAXS * NKV * DD;

    float *pq, *pk, *pv, *pctx;
    __nv_bfloat16 *pahi, *palo, *pwqh, *pwql, *pwoh, *pwol;
    cudaGetSymbolAddress((void**)&pq,   g_q);
    cudaGetSymbolAddress((void**)&pk,   g_k);
    cudaGetSymbolAddress((void**)&pv,   g_v);
    cudaGetSymbolAddress((void**)&pctx, g_ctx);
    cudaGetSymbolAddress((void**)&pahi, g_ahi);
    cudaGetSymbolAddress((void**)&palo, g_alo);
    cudaGetSymbolAddress((void**)&pwqh, g_wqkv_hi);
    cudaGetSymbolAddress((void**)&pwql, g_wqkv_lo);
    cudaGetSymbolAddress((void**)&pwoh, g_wo_hi);
    cudaGetSymbolAddress((void**)&pwol, g_wo_lo);

    const int M = BB * SS;   // 4096

    // 0. weight prep: transpose + bf16 hi/lo split
    transpose_split_kernel<<<dim3(64, 64), 256>>>(Wq, 2048, 0,    pwqh, pwql);
    transpose_split_kernel<<<dim3(64, 16), 256>>>(Wk, 512,  2048, pwqh, pwql);
    transpose_split_kernel<<<dim3(64, 16), 256>>>(Wv, 512,  2560, pwqh, pwql);
    transpose_split_kernel<<<dim3(64, 64), 256>>>(Wo, 2048, 0,    pwoh, pwol);

    // 1. RMSNorm + split
    rmsnorm_split_kernel<<<M, 256>>>(hidden, lnw, pahi, palo);

    // 2. fused QKV GEMM (HMMA)
    cudaFuncSetAttribute(mma_gemm_kernel<0>, cudaFuncAttributeMaxDynamicSharedMemorySize, GSMEM);
    mma_gemm_kernel<0><<<dim3(24, 32), 256, GSMEM>>>(
        pahi, palo, pwqh, pwql, bq, bk, bv, nullptr, pq, pk, pv);

    // 3. RoPE
    {
        int total = BB * SS * (NH + NKV) * (DD / 2);
        rope_kernel<<<(total + 255) / 256, 256>>>(cosb, sinb);
    }

    // 4. KV cache: copy input caches, then scatter new rows
    cudaMemcpyAsync(kc_out, kc_in, (size_t)BB * MAXS * NKV * DD * sizeof(float),
                    cudaMemcpyDeviceToDevice);
    cudaMemcpyAsync(vc_out, vc_in, (size_t)BB * MAXS * NKV * DD * sizeof(float),
                    cudaMemcpyDeviceToDevice);
    {
        int total = BB * SS * NKV * DD;
        scatter_kernel<<<(total + 255) / 256, 256>>>(pos, kc_out, vc_out);
    }

    // 5. Attention
    {
        int smem = ATT_SMEM_FLOATS * (int)sizeof(float);
        cudaFuncSetAttribute(attn_kernel, cudaFuncAttributeMaxDynamicSharedMemorySize, smem);
        attn_kernel<<<dim3(SS / 64, BB * NH), 256, smem>>>();
    }

    // 6. ctx -> bf16 split, then Wo GEMM + residual
    {
        int n = M * HIDN;
        split_kernel<<<(n + 255) / 256, 256>>>(pctx, pahi, palo, n);
    }
    cudaFuncSetAttribute(mma_gemm_kernel<1>, cudaFuncAttributeMaxDynamicSharedMemorySize, GSMEM);
    mma_gemm_kernel<1><<<dim3(16, 32), 256, GSMEM>>>(
        pahi, palo, pwoh, pwol, nullptr, nullptr, nullptr, hidden, out, nullptr, nullptr);
}

// round 7
// speedup vs baseline: 10.2336x; 6.4002x over previous
#include <cuda_runtime.h>
#include <cuda_fp16.h>
#include <math.h>
#include <stdint.h>

#define BB   2
#define SS   2048
#define HIDN 2048
#define NH   16
#define NKV  4
#define DD   128
#define MAXS 4096
#define GEMM_K 2048

// ---------------- scratch ----------------
__device__ __half g_h16 [(size_t)BB*SS*GEMM_K];
__device__ __half g_q16 [(size_t)BB*SS*NH*DD];
__device__ __half g_k16 [(size_t)BB*SS*NKV*DD];
__device__ __half g_v16 [(size_t)BB*SS*NKV*DD];
__device__ __half g_ctx16[(size_t)BB*SS*NH*DD];
__device__ __half g_w16 [(size_t)3072*GEMM_K];
__device__ __half g_wo16[(size_t)2048*GEMM_K];

// ---------------- helpers ----------------
__device__ __forceinline__ uint32_t smem_u32(const void* p) {
    uint32_t a;
    asm("{ .reg .u64 t; cvta.to.shared.u64 t, %1; cvt.u32.u64 %0, t; }" : "=r"(a) : "l"(p));
    return a;
}
__device__ __forceinline__ void cp16(uint32_t dst, const void* src) {
    asm volatile("cp.async.cg.shared.global [%0], [%1], 16;" :: "r"(dst), "l"(src));
}
#define CP_COMMIT() asm volatile("cp.async.commit_group;" ::: "memory")
#define CP_WAIT(n)  asm volatile("cp.async.wait_group %0;" :: "n"(n) : "memory")

__device__ __forceinline__ void ldsm4(uint32_t* r, uint32_t addr) {
    asm volatile("ldmatrix.sync.aligned.m8n8.x4.shared.b16 {%0,%1,%2,%3}, [%4];"
        : "=r"(r[0]), "=r"(r[1]), "=r"(r[2]), "=r"(r[3]) : "r"(addr));
}
__device__ __forceinline__ void ldsm4t(uint32_t* r, uint32_t addr) {
    asm volatile("ldmatrix.sync.aligned.m8n8.x4.trans.shared.b16 {%0,%1,%2,%3}, [%4];"
        : "=r"(r[0]), "=r"(r[1]), "=r"(r[2]), "=r"(r[3]) : "r"(addr));
}
__device__ __forceinline__ void mma16816(float* d, const uint32_t* a, const uint32_t* b) {
    asm volatile(
        "mma.sync.aligned.m16n8k16.row.col.f32.f16.f16.f32 "
        "{%0,%1,%2,%3}, {%4,%5,%6,%7}, {%8,%9}, {%0,%1,%2,%3};"
        : "+f"(d[0]), "+f"(d[1]), "+f"(d[2]), "+f"(d[3])
        : "r"(a[0]), "r"(a[1]), "r"(a[2]), "r"(a[3]), "r"(b[0]), "r"(b[1]));
}

// ---------------- RMSNorm -> fp16 ----------------
__global__ void rmsnorm16_kernel(const float* __restrict__ x,
                                 const float* __restrict__ w,
                                 __half* __restrict__ h)
{
    int row = blockIdx.x;
    const float* xr = x + (size_t)row * HIDN;
    float ss = 0.f;
    for (int i = threadIdx.x; i < HIDN; i += blockDim.x) { float v = xr[i]; ss += v * v; }
    __shared__ float sred[32];
    #pragma unroll
    for (int o = 16; o > 0; o >>= 1) ss += __shfl_xor_sync(0xffffffffu, ss, o);
    if ((threadIdx.x & 31) == 0) sred[threadIdx.x >> 5] = ss;
    __syncthreads();
    if (threadIdx.x < 32) {
        float v = (threadIdx.x < (blockDim.x >> 5)) ? sred[threadIdx.x] : 0.f;
        #pragma unroll
        for (int o = 16; o > 0; o >>= 1) v += __shfl_xor_sync(0xffffffffu, v, o);
        if (threadIdx.x == 0) sred[0] = v;
    }
    __syncthreads();
    float rstd = rsqrtf(sred[0] / (float)HIDN + 1e-6f);
    for (int i = threadIdx.x; i < HIDN; i += blockDim.x)
        h[(size_t)row * HIDN + i] = __float2half_rn(xr[i] * rstd * w[i]);
}

// ---------------- weight transpose + fp16: W[K,Nsrc] -> Wt[n0+n][K] ----------------
__global__ void transpose16_kernel(const float* __restrict__ W, int Nsrc, int n0,
                                   __half* __restrict__ o)
{
    __shared__ float t[32][33];
    int k0 = blockIdx.x * 32, nloc0 = blockIdx.y * 32;
    int tx = threadIdx.x & 31, ty = threadIdx.x >> 5;
    #pragma unroll
    for (int i = 0; i < 4; i++)
        t[ty + i * 8][tx] = W[(size_t)(k0 + ty + i * 8) * Nsrc + nloc0 + tx];
    __syncthreads();
    #pragma unroll
    for (int i = 0; i < 4; i++) {
        int n = nloc0 + ty + i * 8;
        o[(size_t)(n0 + n) * GEMM_K + k0 + tx] = __float2half_rn(t[tx][ty + i * 8]);
    }
}

// ---------------- fp16 HMMA GEMM: C = A @ B^T ----------------
// CTA 128x128, BK=64, 8 warps (2x4), double-buffered cp.async, ldmatrix frags.
#define KSTRB 144                     // smem row stride bytes (72 halves)
#define ATILE (128*KSTRB)             // 18432
#define STAGE (2*ATILE)               // 36864
#define GSMEM (2*STAGE)               // 73728

template<int MODE>   // 0 = QKV (bias, fp16 out), 1 = Wo (residual, fp32 out)
__global__ void __launch_bounds__(256) h16_gemm_kernel(
    const __half* __restrict__ A, const __half* __restrict__ Bm,
    const float* __restrict__ bq, const float* __restrict__ bk, const float* __restrict__ bv,
    const float* __restrict__ resid,
    __half* __restrict__ hq, __half* __restrict__ hk, __half* __restrict__ hv,
    float* __restrict__ outf)
{
    extern __shared__ char smem[];
    uint32_t sb = smem_u32(smem);
    const int tid = threadIdx.x, lane = tid & 31, wid = tid >> 5;
    const int wm = wid >> 2, wn = wid & 3;
    const int g = lane >> 2, c = lane & 3;
    const int lq = lane & 15, lh = lane >> 4;
    const int rowblk = blockIdx.y * 128, colblk = blockIdx.x * 128;

    // cp.async plan: reps 0..3 = A (1024 chunks), 4..7 = B
    const __half* gsrc[8];
    uint32_t soff[8];
    #pragma unroll
    for (int rep = 0; rep < 8; rep++) {
        int lin = (rep & 3) * 256 + tid;
        int row = lin >> 3, sec = lin & 7;
        if (rep < 4) {
            gsrc[rep] = A + (size_t)(rowblk + row) * GEMM_K + sec * 8;
            soff[rep] = (uint32_t)(row * KSTRB + sec * 16);
        } else {
            gsrc[rep] = Bm + (size_t)(colblk + row) * GEMM_K + sec * 8;
            soff[rep] = (uint32_t)(ATILE + row * KSTRB + sec * 16);
        }
    }

    float acc[4][4][4];
    #pragma unroll
    for (int mt = 0; mt < 4; mt++)
        #pragma unroll
        for (int nt = 0; nt < 4; nt++)
            #pragma unroll
            for (int r = 0; r < 4; r++) acc[mt][nt][r] = 0.f;

    #pragma unroll
    for (int rep = 0; rep < 8; rep++) cp16(sb + soff[rep], gsrc[rep]);
    CP_COMMIT();

    const int NCH = GEMM_K / 64;   // 32
    for (int kc = 0; kc < NCH; kc++) {
        if (kc + 1 < NCH) {
            uint32_t stb = sb + (uint32_t)(((kc + 1) & 1) * STAGE);
            #pragma unroll
            for (int rep = 0; rep < 8; rep++)
                cp16(stb + soff[rep], gsrc[rep] + (kc + 1) * 64);
            CP_COMMIT();
            CP_WAIT(1);
        } else {
            CP_WAIT(0);
        }
        __syncthreads();

        uint32_t base = sb + (uint32_t)((kc & 1) * STAGE);
        #pragma unroll
        for (int kk = 0; kk < 4; kk++) {
            uint32_t af[4][4], bf[4][2];
            #pragma unroll
            for (int mt = 0; mt < 4; mt++)
                ldsm4(af[mt], base + (uint32_t)((wm * 64 + mt * 16 + lq) * KSTRB
                                                + (kk * 16 + 8 * lh) * 2));
            #pragma unroll
            for (int ntp = 0; ntp < 2; ntp++) {
                uint32_t r[4];
                ldsm4(r, base + (uint32_t)(ATILE + (wn * 32 + ntp * 16 + lq) * KSTRB
                                           + (kk * 16 + 8 * lh) * 2));
                bf[2 * ntp][0] = r[0]; bf[2 * ntp][1] = r[2];
                bf[2 * ntp + 1][0] = r[1]; bf[2 * ntp + 1][1] = r[3];
            }
            #pragma unroll
            for (int mt = 0; mt < 4; mt++)
                #pragma unroll
                for (int nt = 0; nt < 4; nt++) mma16816(acc[mt][nt], af[mt], bf[nt]);
        }
        __syncthreads();
    }

    // epilogue
    if (MODE == 0) {
        __half* dst; const float* bias; int ncols; int cb0;
        if (colblk < 2048)      { dst = hq; ncols = 2048; cb0 = colblk;        bias = bq + cb0; }
        else if (colblk < 2560) { dst = hk; ncols = 512;  cb0 = colblk - 2048; bias = bk + cb0; }
        else                    { dst = hv; ncols = 512;  cb0 = colblk - 2560; bias = bv + cb0; }
        #pragma unroll
        for (int mt = 0; mt < 4; mt++)
            #pragma unroll
            for (int nt = 0; nt < 4; nt++) {
                int cl = wn * 32 + nt * 8 + 2 * c;
                #pragma unroll
                for (int hf = 0; hf < 2; hf++) {
                    int r = rowblk + wm * 64 + mt * 16 + g + hf * 8;
                    float v0 = acc[mt][nt][hf * 2 + 0] + bias[cl];
                    float v1 = acc[mt][nt][hf * 2 + 1] + bias[cl + 1];
                    *(__half2*)(dst + (size_t)r * ncols + cb0 + cl) = __floats2half2_rn(v0, v1);
                }
            }
    } else {
        #pragma unroll
        for (int mt = 0; mt < 4; mt++)
            #pragma unroll
            for (int nt = 0; nt < 4; nt++) {
                int cl = wn * 32 + nt * 8 + 2 * c;
                #pragma unroll
                for (int hf = 0; hf < 2; hf++) {
                    int r = rowblk + wm * 64 + mt * 16 + g + hf * 8;
                    const float* res = resid + (size_t)r * 2048 + colblk + cl;
                    float v0 = acc[mt][nt][hf * 2 + 0] + res[0];
                    float v1 = acc[mt][nt][hf * 2 + 1] + res[1];
                    *(float2*)(outf + (size_t)r * 2048 + colblk + cl) = make_float2(v0, v1);
                }
            }
    }
}

// ---------------- RoPE on fp16 q (with scale) and k ----------------
__global__ void rope16_kernel(const float* __restrict__ cosb, const float* __restrict__ sinb)
{
    int idx = blockIdx.x * blockDim.x + threadIdx.x;
    const int perbs = (NH + NKV) * (DD / 2);
    const int total = BB * SS * perbs;
    if (idx >= total) return;
    int bs = idx / perbs, r = idx % perbs;
    const float* cp = cosb + (size_t)bs * DD;
    const float* sp = sinb + (size_t)bs * DD;
    __half* ptr; int i; float postscale;
    if (r < NH * (DD / 2)) {
        int h = r / (DD / 2); i = r % (DD / 2);
        ptr = g_q16 + (((size_t)bs) * NH + h) * DD;
        postscale = 0.08838834764831845f;
    } else {
        int rr = r - NH * (DD / 2);
        int h = rr / (DD / 2); i = rr % (DD / 2);
        ptr = g_k16 + (((size_t)bs) * NKV + h) * DD;
        postscale = 1.0f;
    }
    __half2 v = ((__half2*)ptr)[i];
    float x0 = __half2float(v.x), x1 = __half2float(v.y);
    float c0 = cp[2 * i], s0 = sp[2 * i];
    float c1 = cp[2 * i + 1], s1 = sp[2 * i + 1];
    float y0 = (x0 * c0 - x1 * s0) * postscale;
    float y1 = (x1 * c1 + x0 * s1) * postscale;
    ((__half2*)ptr)[i] = __floats2half2_rn(y0, y1);
}

// ---------------- KV cache scatter (fp16 -> fp32 caches) ----------------
__global__ void scatter16_kernel(const int* __restrict__ pos,
                                 float* __restrict__ kc, float* __restrict__ vc)
{
    int idx = blockIdx.x * blockDim.x + threadIdx.x;
    const int total = BB * SS * NKV * DD;
    if (idx >= total) return;
    int d = idx % DD; int t = idx / DD;
    int kv = t % NKV; t /= NKV;
    int s = t % SS; int b = t / SS;
    int p = pos[s];
    size_t dst = (((size_t)b * MAXS + p) * NKV + kv) * DD + d;
    kc[dst] = __half2float(g_k16[idx]);
    vc[dst] = __half2float(g_v16[idx]);
}

// ---------------- FA2 attention: BM=128 (8 warps), BN=64, D=128, fp16 HMMA ----------------
#define AKSTR 272                      // bytes per smem row (136 halves)
#define QBYTES (128*AKSTR)             // 34816
#define KVBYTES (64*AKSTR)             // 17408
#define AOFF_K(s) (QBYTES + (s)*2*KVBYTES)
#define AOFF_V(s) (QBYTES + (s)*2*KVBYTES + KVBYTES)
#define ASMEM (QBYTES + 4*KVBYTES)     // 104448

__global__ void __launch_bounds__(256) attn16_kernel()
{
    extern __shared__ char smem[];
    uint32_t sb = smem_u32(smem);
    const int tid = threadIdx.x, lane = tid & 31, w = tid >> 5;
    const int g = lane >> 2, c = lane & 3;
    const int lq = lane & 15, lh = lane >> 4;
    const int qt = (int)(gridDim.x - 1 - blockIdx.x);
    const int bh = blockIdx.y, b = bh >> 4, h = bh & 15, kvh = h >> 2;

    // Q cp.async: 8 chunks/thread
    #pragma unroll
    for (int rep = 0; rep < 8; rep++) {
        int lin = rep * 256 + tid;
        int row = lin >> 4, sec = lin & 15;
        const __half* src = g_q16 + (((size_t)(b * SS + qt * 128 + row)) * NH + h) * DD + sec * 8;
        cp16(sb + (uint32_t)(row * AKSTR + sec * 16), src);
    }
    // K0/V0
    #pragma unroll
    for (int rep = 0; rep < 4; rep++) {
        int lin = rep * 256 + tid;
        int row = lin >> 4, sec = lin & 15;
        cp16(sb + (uint32_t)(AOFF_K(0) + row * AKSTR + sec * 16),
             g_k16 + (((size_t)(b * SS + row)) * NKV + kvh) * DD + sec * 8);
        cp16(sb + (uint32_t)(AOFF_V(0) + row * AKSTR + sec * 16),
             g_v16 + (((size_t)(b * SS + row)) * NKV + kvh) * DD + sec * 8);
    }
    CP_COMMIT();

    uint32_t qf[8][4];
    float O[16][4];
    #pragma unroll
    for (int j = 0; j < 16; j++)
        #pragma unroll
        for (int r = 0; r < 4; r++) O[j][r] = 0.f;
    float m0 = -1e30f, m1 = -1e30f, l0 = 0.f, l1 = 0.f;

    const int last = 2 * qt + 1;
    for (int kt = 0; kt <= last; kt++) {
        if (kt < last) {
            int st = (kt + 1) & 1;
            #pragma unroll
            for (int rep = 0; rep < 4; rep++) {
                int lin = rep * 256 + tid;
                int row = lin >> 4, sec = lin & 15;
                int s = (kt + 1) * 64 + row;
                cp16(sb + (uint32_t)(AOFF_K(st) + row * AKSTR + sec * 16),
                     g_k16 + (((size_t)(b * SS + s)) * NKV + kvh) * DD + sec * 8);
                cp16(sb + (uint32_t)(AOFF_V(st) + row * AKSTR + sec * 16),
                     g_v16 + (((size_t)(b * SS + s)) * NKV + kvh) * DD + sec * 8);
            }
            CP_COMMIT();
            CP_WAIT(1);
        } else {
            CP_WAIT(0);
        }
        __syncthreads();

        if (kt == 0) {
            #pragma unroll
            for (int kk = 0; kk < 8; kk++)
                ldsm4(qf[kk], sb + (uint32_t)((w * 16 + lq) * AKSTR + (kk * 16 + 8 * lh) * 2));
        }

        int cur = kt & 1;
        // S = Q K^T
        float s[8][4];
        #pragma unroll
        for (int j = 0; j < 8; j++)
            #pragma unroll
            for (int r = 0; r < 4; r++) s[j][r] = 0.f;
        #pragma unroll
        for (int kk = 0; kk < 8; kk++) {
            #pragma unroll
            for (int j2 = 0; j2 < 4; j2++) {
                uint32_t r[4];
                ldsm4(r, sb + (uint32_t)(AOFF_K(cur) + (j2 * 16 + lq) * AKSTR
                                         + (kk * 16 + 8 * lh) * 2));
                uint32_t b0[2] = { r[0], r[2] }, b1[2] = { r[1], r[3] };
                mma16816(s[2 * j2], qf[kk], b0);
                mma16816(s[2 * j2 + 1], qf[kk], b1);
            }
        }
        // causal mask (diagonal band tiles only)
        if (kt * 64 + 63 > qt * 128 + w * 16) {
            int row0 = qt * 128 + w * 16 + g;
            #pragma unroll
            for (int j = 0; j < 8; j++) {
                int col = kt * 64 + j * 8 + 2 * c;
                if (col > row0)         s[j][0] = -1e30f;
                if (col + 1 > row0)     s[j][1] = -1e30f;
                if (col > row0 + 8)     s[j][2] = -1e30f;
                if (col + 1 > row0 + 8) s[j][3] = -1e30f;
            }
        }
        // online softmax
        float r0 = -1e30f, r1 = -1e30f;
        #pragma unroll
        for (int j = 0; j < 8; j++) {
            r0 = fmaxf(r0, fmaxf(s[j][0], s[j][1]));
            r1 = fmaxf(r1, fmaxf(s[j][2], s[j][3]));
        }
        r0 = fmaxf(r0, __shfl_xor_sync(0xffffffffu, r0, 1));
        r0 = fmaxf(r0, __shfl_xor_sync(0xffffffffu, r0, 2));
        r1 = fmaxf(r1, __shfl_xor_sync(0xffffffffu, r1, 1));
        r1 = fmaxf(r1, __shfl_xor_sync(0xffffffffu, r1, 2));
        float mn0 = fmaxf(m0, r0), mn1 = fmaxf(m1, r1);
        float a0 = __expf(m0 - mn0), a1 = __expf(m1 - mn1);
        m0 = mn0; m1 = mn1;
        float sum0 = 0.f, sum1 = 0.f;
        #pragma unroll
        for (int j = 0; j < 8; j++) {
            s[j][0] = __expf(s[j][0] - mn0);
            s[j][1] = __expf(s[j][1] - mn0);
            s[j][2] = __expf(s[j][2] - mn1);
            s[j][3] = __expf(s[j][3] - mn1);
            sum0 += s[j][0] + s[j][1];
            sum1 += s[j][2] + s[j][3];
        }
        sum0 += __shfl_xor_sync(0xffffffffu, sum0, 1);
        sum0 += __shfl_xor_sync(0xffffffffu, sum0, 2);
        sum1 += __shfl_xor_sync(0xffffffffu, sum1, 1);
        sum1 += __shfl_xor_sync(0xffffffffu, sum1, 2);
        l0 = l0 * a0 + sum0;
        l1 = l1 * a1 + sum1;
        #pragma unroll
        for (int j = 0; j < 16; j++) {
            O[j][0] *= a0; O[j][1] *= a0;
            O[j][2] *= a1; O[j][3] *= a1;
        }
        // O += P V
        #pragma unroll
        for (int kk2 = 0; kk2 < 4; kk2++) {
            uint32_t pa[4];
            __half2 h0 = __floats2half2_rn(s[2 * kk2][0], s[2 * kk2][1]);
            __half2 h1 = __floats2half2_rn(s[2 * kk2][2], s[2 * kk2][3]);
            __half2 h2 = __floats2half2_rn(s[2 * kk2 + 1][0], s[2 * kk2 + 1][1]);
            __half2 h3 = __floats2half2_rn(s[2 * kk2 + 1][2], s[2 * kk2 + 1][3]);
            pa[0] = *(uint32_t*)&h0; pa[1] = *(uint32_t*)&h1;
            pa[2] = *(uint32_t*)&h2; pa[3] = *(uint32_t*)&h3;
            #pragma unroll
            for (int j2 = 0; j2 < 8; j2++) {
                uint32_t r[4];
                ldsm4t(r, sb + (uint32_t)(AOFF_V(cur) + (kk2 * 16 + lq) * AKSTR
                                          + (j2 * 16 + 8 * lh) * 2));
                mma16816(O[2 * j2], pa, r);
                mma16816(O[2 * j2 + 1], pa, r + 2);
            }
        }
        __syncthreads();
    }

    float inv0 = 1.f / l0, inv1 = 1.f / l1;
    int row0 = qt * 128 + w * 16 + g;
    __half* op0 = g_ctx16 + (((size_t)(b * SS + row0)) * NH + h) * DD;
    __half* op1 = g_ctx16 + (((size_t)(b * SS + row0 + 8)) * NH + h) * DD;
    #pragma unroll
    for (int j = 0; j < 16; j++) {
        int col = j * 8 + 2 * c;
        *(__half2*)(op0 + col) = __floats2half2_rn(O[j][0] * inv0, O[j][1] * inv0);
        *(__half2*)(op1 + col) = __floats2half2_rn(O[j][2] * inv1, O[j][3] * inv1);
    }
}

// ---------------- launch ----------------
extern "C" void kernel_launch(void* const* d_in, const int* in_sizes, int n_in,
                              void* d_out, int out_size)
{
    const float* hidden = (const float*)d_in[0];
    const float* lnw    = (const float*)d_in[1];
    const float* Wq     = (const float*)d_in[2];
    const float* bq     = (const float*)d_in[3];
    const float* Wk     = (const float*)d_in[4];
    const float* bk     = (const float*)d_in[5];
    const float* Wv     = (const float*)d_in[6];
    const float* bv     = (const float*)d_in[7];
    const float* Wo     = (const float*)d_in[8];
    const float* cosb   = (const float*)d_in[9];
    const float* sinb   = (const float*)d_in[10];
    const float* kc_in  = (const float*)d_in[11];
    const float* vc_in  = (const float*)d_in[12];
    const int*   pos    = (const int*)d_in[13];

    float* out    = (float*)d_out;
    float* kc_out = out + (size_t)BB * SS * HIDN;
    float* vc_out = kc_out + (size_t)BB * MAXS * NKV * DD;

    __half *ph, *pq, *pk, *pv, *pctx, *pw, *pwo;
    cudaGetSymbolAddress((void**)&ph,   g_h16);
    cudaGetSymbolAddress((void**)&pq,   g_q16);
    cudaGetSymbolAddress((void**)&pk,   g_k16);
    cudaGetSymbolAddress((void**)&pv,   g_v16);
    cudaGetSymbolAddress((void**)&pctx, g_ctx16);
    cudaGetSymbolAddress((void**)&pw,   g_w16);
    cudaGetSymbolAddress((void**)&pwo,  g_wo16);

    const int M = BB * SS;   // 4096

    // 0. weight prep
    transpose16_kernel<<<dim3(64, 64), 256>>>(Wq, 2048, 0,    pw);
    transpose16_kernel<<<dim3(64, 16), 256>>>(Wk, 512,  2048, pw);
    transpose16_kernel<<<dim3(64, 16), 256>>>(Wv, 512,  2560, pw);
    transpose16_kernel<<<dim3(64, 64), 256>>>(Wo, 2048, 0,    pwo);

    // 1. RMSNorm -> fp16
    rmsnorm16_kernel<<<M, 256>>>(hidden, lnw, ph);

    // 2. fused QKV GEMM
    cudaFuncSetAttribute(h16_gemm_kernel<0>, cudaFuncAttributeMaxDynamicSharedMemorySize, GSMEM);
    h16_gemm_kernel<0><<<dim3(24, 32), 256, GSMEM>>>(
        ph, pw, bq, bk, bv, nullptr, pq, pk, pv, nullptr);

    // 3. RoPE (q gets 1/sqrt(D) folded in)
    {
        int total = BB * SS * (NH + NKV) * (DD / 2);
        rope16_kernel<<<(total + 255) / 256, 256>>>(cosb, sinb);
    }

    // 4. KV caches
    cudaMemcpyAsync(kc_out, kc_in, (size_t)BB * MAXS * NKV * DD * sizeof(float),
                    cudaMemcpyDeviceToDevice);
    cudaMemcpyAsync(vc_out, vc_in, (size_t)BB * MAXS * NKV * DD * sizeof(float),
                    cudaMemcpyDeviceToDevice);
    {
        int total = BB * SS * NKV * DD;
        scatter16_kernel<<<(total + 255) / 256, 256>>>(pos, kc_out, vc_out);
    }

    // 5. attention
    cudaFuncSetAttribute(attn16_kernel, cudaFuncAttributeMaxDynamicSharedMemorySize, ASMEM);
    attn16_kernel<<<dim3(SS / 128, BB * NH), 256, ASMEM>>>();

    // 6. Wo GEMM + residual
    cudaFuncSetAttribute(h16_gemm_kernel<1>, cudaFuncAttributeMaxDynamicSharedMemorySize, GSMEM);
    h16_gemm_kernel<1><<<dim3(16, 32), 256, GSMEM>>>(
        pctx, pwo, nullptr, nullptr, nullptr, hidden, nullptr, nullptr, nullptr, out);
}

// round 9
// speedup vs baseline: 11.5039x; 1.1241x over previous
#include <cuda_runtime.h>
#include <cuda_fp16.h>
#include <math.h>
#include <stdint.h>

#define BB   2
#define SS   2048
#define HIDN 2048
#define NH   16
#define NKV  4
#define DD   128
#define MAXS 4096
#define GEMM_K 2048
#define QSCALE 0.08838834764831845f
#define L2E 1.4426950408889634f

// ---------------- scratch ----------------
__device__ __half g_h16 [(size_t)BB*SS*GEMM_K];
__device__ __half g_q16 [(size_t)BB*SS*NH*DD];
__device__ __half g_k16 [(size_t)BB*SS*NKV*DD];
__device__ __half g_v16 [(size_t)BB*SS*NKV*DD];
__device__ __half g_ctx16[(size_t)BB*SS*NH*DD];
__device__ __half g_w16 [(size_t)3072*GEMM_K];
__device__ __half g_wo16[(size_t)2048*GEMM_K];

// ---------------- helpers ----------------
__device__ __forceinline__ uint32_t smem_u32(const void* p) {
    uint32_t a;
    asm("{ .reg .u64 t; cvta.to.shared.u64 t, %1; cvt.u32.u64 %0, t; }" : "=r"(a) : "l"(p));
    return a;
}
__device__ __forceinline__ void cp16(uint32_t dst, const void* src) {
    asm volatile("cp.async.cg.shared.global [%0], [%1], 16;" :: "r"(dst), "l"(src));
}
#define CP_COMMIT() asm volatile("cp.async.commit_group;" ::: "memory")
#define CP_WAIT(n)  asm volatile("cp.async.wait_group %0;" :: "n"(n) : "memory")

__device__ __forceinline__ void ldsm4(uint32_t* r, uint32_t addr) {
    asm volatile("ldmatrix.sync.aligned.m8n8.x4.shared.b16 {%0,%1,%2,%3}, [%4];"
        : "=r"(r[0]), "=r"(r[1]), "=r"(r[2]), "=r"(r[3]) : "r"(addr));
}
__device__ __forceinline__ void ldsm4t(uint32_t* r, uint32_t addr) {
    asm volatile("ldmatrix.sync.aligned.m8n8.x4.trans.shared.b16 {%0,%1,%2,%3}, [%4];"
        : "=r"(r[0]), "=r"(r[1]), "=r"(r[2]), "=r"(r[3]) : "r"(addr));
}
__device__ __forceinline__ void mma16816(float* d, const uint32_t* a, const uint32_t* b) {
    asm volatile(
        "mma.sync.aligned.m16n8k16.row.col.f32.f16.f16.f32 "
        "{%0,%1,%2,%3}, {%4,%5,%6,%7}, {%8,%9}, {%0,%1,%2,%3};"
        : "+f"(d[0]), "+f"(d[1]), "+f"(d[2]), "+f"(d[3])
        : "r"(a[0]), "r"(a[1]), "r"(a[2]), "r"(a[3]), "r"(b[0]), "r"(b[1]));
}
// exp(t*ln2) for two floats -> packed half2 (lo = t0)
__device__ __forceinline__ uint32_t expx2_h2(float t0, float t1) {
    uint32_t h;
    asm("cvt.rn.f16x2.f32 %0, %1, %2;" : "=r"(h) : "f"(t1), "f"(t0));
    asm("ex2.approx.f16x2 %0, %0;" : "+r"(h));
    return h;
}

// ---------------- RMSNorm -> fp16 ----------------
__global__ void rmsnorm16_kernel(const float* __restrict__ x,
                                 const float* __restrict__ w,
                                 __half* __restrict__ h)
{
    int row = blockIdx.x;
    const float* xr = x + (size_t)row * HIDN;
    float ss = 0.f;
    for (int i = threadIdx.x; i < HIDN; i += blockDim.x) { float v = xr[i]; ss += v * v; }
    __shared__ float sred[32];
    #pragma unroll
    for (int o = 16; o > 0; o >>= 1) ss += __shfl_xor_sync(0xffffffffu, ss, o);
    if ((threadIdx.x & 31) == 0) sred[threadIdx.x >> 5] = ss;
    __syncthreads();
    if (threadIdx.x < 32) {
        float v = (threadIdx.x < (blockDim.x >> 5)) ? sred[threadIdx.x] : 0.f;
        #pragma unroll
        for (int o = 16; o > 0; o >>= 1) v += __shfl_xor_sync(0xffffffffu, v, o);
        if (threadIdx.x == 0) sred[0] = v;
    }
    __syncthreads();
    float rstd = rsqrtf(sred[0] / (float)HIDN + 1e-6f);
    for (int i = threadIdx.x; i < HIDN; i += blockDim.x)
        h[(size_t)row * HIDN + i] = __float2half_rn(xr[i] * rstd * w[i]);
}

// ---------------- fused QKV weight transpose -> fp16 Wt[n][K] ----------------
__global__ void transpose_qkv_kernel(const float* __restrict__ Wq,
                                     const float* __restrict__ Wk,
                                     const float* __restrict__ Wv,
                                     __half* __restrict__ o)
{
    __shared__ float t[32][33];
    int k0 = blockIdx.x * 32, ng0 = blockIdx.y * 32;
    const float* W; int Nsrc; int nsrc0;
    if (ng0 < 2048)      { W = Wq; Nsrc = 2048; nsrc0 = ng0; }
    else if (ng0 < 2560) { W = Wk; Nsrc = 512;  nsrc0 = ng0 - 2048; }
    else                 { W = Wv; Nsrc = 512;  nsrc0 = ng0 - 2560; }
    int tx = threadIdx.x & 31, ty = threadIdx.x >> 5;
    #pragma unroll
    for (int i = 0; i < 4; i++)
        t[ty + i * 8][tx] = W[(size_t)(k0 + ty + i * 8) * Nsrc + nsrc0 + tx];
    __syncthreads();
    #pragma unroll
    for (int i = 0; i < 4; i++)
        o[(size_t)(ng0 + ty + i * 8) * GEMM_K + k0 + tx] = __float2half_rn(t[tx][ty + i * 8]);
}

__global__ void transpose_wo_kernel(const float* __restrict__ W, __half* __restrict__ o)
{
    __shared__ float t[32][33];
    int k0 = blockIdx.x * 32, n0 = blockIdx.y * 32;
    int tx = threadIdx.x & 31, ty = threadIdx.x >> 5;
    #pragma unroll
    for (int i = 0; i < 4; i++)
        t[ty + i * 8][tx] = W[(size_t)(k0 + ty + i * 8) * 2048 + n0 + tx];
    __syncthreads();
    #pragma unroll
    for (int i = 0; i < 4; i++)
        o[(size_t)(n0 + ty + i * 8) * GEMM_K + k0 + tx] = __float2half_rn(t[tx][ty + i * 8]);
}

// ---------------- fp16 HMMA GEMM: C = A @ B^T ----------------
// CTA 128x128, BK=64, 8 warps (2x4), double-buffered cp.async, ldmatrix frags.
#define KSTRB 144
#define ATILE (128*KSTRB)
#define STAGE (2*ATILE)
#define GSMEM (2*STAGE)

template<int MODE>   // 0 = QKV (bias + rope + cache), 1 = Wo (residual, fp32 out)
__global__ void __launch_bounds__(256) h16_gemm_kernel(
    const __half* __restrict__ A, const __half* __restrict__ Bm,
    const float* __restrict__ bq, const float* __restrict__ bk, const float* __restrict__ bv,
    const float* __restrict__ resid,
    const float* __restrict__ cosb, const float* __restrict__ sinb,
    const int* __restrict__ pos,
    float* __restrict__ kcache, float* __restrict__ vcache,
    float* __restrict__ outf)
{
    extern __shared__ char smem[];
    uint32_t sb = smem_u32(smem);
    const int tid = threadIdx.x, lane = tid & 31, wid = tid >> 5;
    const int wm = wid >> 2, wn = wid & 3;
    const int g = lane >> 2, c = lane & 3;
    const int lq = lane & 15, lh = lane >> 4;
    const int rowblk = blockIdx.y * 128, colblk = blockIdx.x * 128;

    const __half* gsrc[8];
    uint32_t soff[8];
    #pragma unroll
    for (int rep = 0; rep < 8; rep++) {
        int lin = (rep & 3) * 256 + tid;
        int row = lin >> 3, sec = lin & 7;
        if (rep < 4) {
            gsrc[rep] = A + (size_t)(rowblk + row) * GEMM_K + sec * 8;
            soff[rep] = (uint32_t)(row * KSTRB + sec * 16);
        } else {
            gsrc[rep] = Bm + (size_t)(colblk + row) * GEMM_K + sec * 8;
            soff[rep] = (uint32_t)(ATILE + row * KSTRB + sec * 16);
        }
    }

    float acc[4][4][4];
    #pragma unroll
    for (int mt = 0; mt < 4; mt++)
        #pragma unroll
        for (int nt = 0; nt < 4; nt++)
            #pragma unroll
            for (int r = 0; r < 4; r++) acc[mt][nt][r] = 0.f;

    #pragma unroll
    for (int rep = 0; rep < 8; rep++) cp16(sb + soff[rep], gsrc[rep]);
    CP_COMMIT();

    const int NCH = GEMM_K / 64;
    for (int kc = 0; kc < NCH; kc++) {
        if (kc + 1 < NCH) {
            uint32_t stb = sb + (uint32_t)(((kc + 1) & 1) * STAGE);
            #pragma unroll
            for (int rep = 0; rep < 8; rep++)
                cp16(stb + soff[rep], gsrc[rep] + (kc + 1) * 64);
            CP_COMMIT();
            CP_WAIT(1);
        } else {
            CP_WAIT(0);
        }
        __syncthreads();

        uint32_t base = sb + (uint32_t)((kc & 1) * STAGE);
        #pragma unroll
        for (int kk = 0; kk < 4; kk++) {
            uint32_t af[4][4], bf[4][2];
            #pragma unroll
            for (int mt = 0; mt < 4; mt++)
                ldsm4(af[mt], base + (uint32_t)((wm * 64 + mt * 16 + lq) * KSTRB
                                                + (kk * 16 + 8 * lh) * 2));
            #pragma unroll
            for (int ntp = 0; ntp < 2; ntp++) {
                uint32_t r[4];
                ldsm4(r, base + (uint32_t)(ATILE + (wn * 32 + ntp * 16 + lq) * KSTRB
                                           + (kk * 16 + 8 * lh) * 2));
                bf[2 * ntp][0] = r[0]; bf[2 * ntp][1] = r[2];
                bf[2 * ntp + 1][0] = r[1]; bf[2 * ntp + 1][1] = r[3];
            }
            #pragma unroll
            for (int mt = 0; mt < 4; mt++)
                #pragma unroll
                for (int nt = 0; nt < 4; nt++) mma16816(acc[mt][nt], af[mt], bf[nt]);
        }
        __syncthreads();
    }

    if (MODE == 0) {
        int cls = (colblk < 2048) ? 0 : (colblk < 2560 ? 1 : 2);
        #pragma unroll
        for (int mt = 0; mt < 4; mt++)
            #pragma unroll
            for (int nt = 0; nt < 4; nt++) {
                int cl = wn * 32 + nt * 8 + 2 * c;
                int gcol = colblk + cl;
                #pragma unroll
                for (int hf = 0; hf < 2; hf++) {
                    int r = rowblk + wm * 64 + mt * 16 + g + hf * 8;
                    float v0 = acc[mt][nt][hf * 2 + 0];
                    float v1 = acc[mt][nt][hf * 2 + 1];
                    if (cls == 0) {
                        int hh = gcol >> 7, d = gcol & 127;
                        v0 += bq[gcol]; v1 += bq[gcol + 1];
                        float c0 = cosb[(size_t)r * DD + d],     s0 = sinb[(size_t)r * DD + d];
                        float c1 = cosb[(size_t)r * DD + d + 1], s1 = sinb[(size_t)r * DD + d + 1];
                        float y0 = (v0 * c0 - v1 * s0) * QSCALE;
                        float y1 = (v1 * c1 + v0 * s1) * QSCALE;
                        *(__half2*)(g_q16 + ((size_t)r * NH + hh) * DD + d) = __floats2half2_rn(y0, y1);
                    } else if (cls == 1) {
                        int col = gcol - 2048, kvh = col >> 7, d = col & 127;
                        v0 += bk[col]; v1 += bk[col + 1];
                        float c0 = cosb[(size_t)r * DD + d],     s0 = sinb[(size_t)r * DD + d];
                        float c1 = cosb[(size_t)r * DD + d + 1], s1 = sinb[(size_t)r * DD + d + 1];
                        float y0 = v0 * c0 - v1 * s0;
                        float y1 = v1 * c1 + v0 * s1;
                        *(__half2*)(g_k16 + ((size_t)r * NKV + kvh) * DD + d) = __floats2half2_rn(y0, y1);
                        int bb = r >> 11, sl = r & 2047;
                        int p = pos[sl];
                        *(float2*)(kcache + (((size_t)bb * MAXS + p) * NKV + kvh) * DD + d) =
                            make_float2(y0, y1);
                    } else {
                        int col = gcol - 2560, kvh = col >> 7, d = col & 127;
                        v0 += bv[col]; v1 += bv[col + 1];
                        *(__half2*)(g_v16 + ((size_t)r * NKV + kvh) * DD + d) = __floats2half2_rn(v0, v1);
                        int bb = r >> 11, sl = r & 2047;
                        int p = pos[sl];
                        *(float2*)(vcache + (((size_t)bb * MAXS + p) * NKV + kvh) * DD + d) =
                            make_float2(v0, v1);
                    }
                }
            }
    } else {
        #pragma unroll
        for (int mt = 0; mt < 4; mt++)
            #pragma unroll
            for (int nt = 0; nt < 4; nt++) {
                int cl = wn * 32 + nt * 8 + 2 * c;
                #pragma unroll
                for (int hf = 0; hf < 2; hf++) {
                    int r = rowblk + wm * 64 + mt * 16 + g + hf * 8;
                    const float* res = resid + (size_t)r * 2048 + colblk + cl;
                    float v0 = acc[mt][nt][hf * 2 + 0] + res[0];
                    float v1 = acc[mt][nt][hf * 2 + 1] + res[1];
                    *(float2*)(outf + (size_t)r * 2048 + colblk + cl) = make_float2(v0, v1);
                }
            }
    }
}

// ---------------- FA2 attention: BM=128, BN=128, D=128, fp16 HMMA ----------------
#define AKSTR 272
#define QB (128*AKSTR)
#define KVB (128*AKSTR)
#define KOFF(s) (QB + (s)*2*KVB)
#define VOFF(s) (QB + (s)*2*KVB + KVB)
#define ASMEM (QB + 4*KVB)             // 174080

__global__ void __launch_bounds__(256) attn16_kernel()
{
    extern __shared__ char smem[];
    uint32_t sb = smem_u32(smem);
    const int tid = threadIdx.x, lane = tid & 31, w = tid >> 5;
    const int g = lane >> 2, c = lane & 3;
    const int lq = lane & 15, lh = lane >> 4;
    const int idx = blockIdx.x;
    const int qt = 15 - (idx >> 5);            // heavy CTAs first
    const int bh = idx & 31, b = bh >> 4, h = bh & 15, kvh = h >> 2;

    // Q (128 rows) + K0/V0
    #pragma unroll
    for (int rep = 0; rep < 8; rep++) {
        int lin = rep * 256 + tid;
        int row = lin >> 4, sec = lin & 15;
        cp16(sb + (uint32_t)(row * AKSTR + sec * 16),
             g_q16 + (((size_t)(b * SS + qt * 128 + row)) * NH + h) * DD + sec * 8);
        cp16(sb + (uint32_t)(KOFF(0) + row * AKSTR + sec * 16),
             g_k16 + (((size_t)(b * SS + row)) * NKV + kvh) * DD + sec * 8);
        cp16(sb + (uint32_t)(VOFF(0) + row * AKSTR + sec * 16),
             g_v16 + (((size_t)(b * SS + row)) * NKV + kvh) * DD + sec * 8);
    }
    CP_COMMIT();

    uint32_t qf[8][4];
    float O[16][4];
    #pragma unroll
    for (int j = 0; j < 16; j++)
        #pragma unroll
        for (int r = 0; r < 4; r++) O[j][r] = 0.f;
    float ls[4] = {0.f, 0.f, 0.f, 0.f};
    float m0 = -1e30f, m1 = -1e30f;
    const uint32_t ONE2 = 0x3C003C00u;

    const int nkt = qt + 1;
    for (int kt = 0; kt < nkt; kt++) {
        if (kt + 1 < nkt) {
            int st = (kt + 1) & 1;
            #pragma unroll
            for (int rep = 0; rep < 8; rep++) {
                int lin = rep * 256 + tid;
                int row = lin >> 4, sec = lin & 15;
                int s = (kt + 1) * 128 + row;
                cp16(sb + (uint32_t)(KOFF(st) + row * AKSTR + sec * 16),
                     g_k16 + (((size_t)(b * SS + s)) * NKV + kvh) * DD + sec * 8);
                cp16(sb + (uint32_t)(VOFF(st) + row * AKSTR + sec * 16),
                     g_v16 + (((size_t)(b * SS + s)) * NKV + kvh) * DD + sec * 8);
            }
            CP_COMMIT();
            CP_WAIT(1);
        } else {
            CP_WAIT(0);
        }
        __syncthreads();

        if (kt == 0) {
            #pragma unroll
            for (int kk = 0; kk < 8; kk++)
                ldsm4(qf[kk], sb + (uint32_t)((w * 16 + lq) * AKSTR + (kk * 16 + 8 * lh) * 2));
        }
        int cur = kt & 1;

        // S = Q K^T  (16 x 128 per warp)
        float s[16][4];
        #pragma unroll
        for (int j = 0; j < 16; j++)
            #pragma unroll
            for (int r = 0; r < 4; r++) s[j][r] = 0.f;
        #pragma unroll
        for (int kk = 0; kk < 8; kk++) {
            #pragma unroll
            for (int j2 = 0; j2 < 8; j2++) {
                uint32_t r[4];
                ldsm4(r, sb + (uint32_t)(KOFF(cur) + (j2 * 16 + lq) * AKSTR
                                         + (kk * 16 + 8 * lh) * 2));
                uint32_t b0[2] = { r[0], r[2] }, b1[2] = { r[1], r[3] };
                mma16816(s[2 * j2], qf[kk], b0);
                mma16816(s[2 * j2 + 1], qf[kk], b1);
            }
        }
        // causal mask (diagonal tile only)
        if (kt == qt) {
            int row0 = qt * 128 + w * 16 + g;
            #pragma unroll
            for (int j = 0; j < 16; j++) {
                int col = kt * 128 + j * 8 + 2 * c;
                if (col > row0)         s[j][0] = -1e30f;
                if (col + 1 > row0)     s[j][1] = -1e30f;
                if (col > row0 + 8)     s[j][2] = -1e30f;
                if (col + 1 > row0 + 8) s[j][3] = -1e30f;
            }
        }
        // row max
        float r0 = -1e30f, r1 = -1e30f;
        #pragma unroll
        for (int j = 0; j < 16; j++) {
            r0 = fmaxf(r0, fmaxf(s[j][0], s[j][1]));
            r1 = fmaxf(r1, fmaxf(s[j][2], s[j][3]));
        }
        r0 = fmaxf(r0, __shfl_xor_sync(0xffffffffu, r0, 1));
        r0 = fmaxf(r0, __shfl_xor_sync(0xffffffffu, r0, 2));
        r1 = fmaxf(r1, __shfl_xor_sync(0xffffffffu, r1, 1));
        r1 = fmaxf(r1, __shfl_xor_sync(0xffffffffu, r1, 2));
        float mn0 = fmaxf(m0, r0), mn1 = fmaxf(m1, r1);
        float a0 = __expf(m0 - mn0), a1 = __expf(m1 - mn1);
        m0 = mn0; m1 = mn1;
        float nl0 = mn0 * L2E, nl1 = mn1 * L2E;

        // P = exp(S - m) as packed half2 (fp16 ex2)
        uint32_t ph[16][2];
        #pragma unroll
        for (int j = 0; j < 16; j++) {
            ph[j][0] = expx2_h2(fmaf(s[j][0], L2E, -nl0), fmaf(s[j][1], L2E, -nl0));
            ph[j][1] = expx2_h2(fmaf(s[j][2], L2E, -nl1), fmaf(s[j][3], L2E, -nl1));
        }
        // rescale O and running sums
        #pragma unroll
        for (int j = 0; j < 16; j++) {
            O[j][0] *= a0; O[j][1] *= a0;
            O[j][2] *= a1; O[j][3] *= a1;
        }
        ls[0] *= a0; ls[1] *= a0; ls[2] *= a1; ls[3] *= a1;

        // sums via P @ ones, O += P V
        uint32_t bone[2] = { ONE2, ONE2 };
        #pragma unroll
        for (int kk2 = 0; kk2 < 8; kk2++) {
            uint32_t pa[4] = { ph[2 * kk2][0], ph[2 * kk2][1],
                               ph[2 * kk2 + 1][0], ph[2 * kk2 + 1][1] };
            mma16816(ls, pa, bone);
            #pragma unroll
            for (int j2 = 0; j2 < 8; j2++) {
                uint32_t r[4];
                ldsm4t(r, sb + (uint32_t)(VOFF(cur) + (kk2 * 16 + lq) * AKSTR
                                          + (j2 * 16 + 8 * lh) * 2));
                mma16816(O[2 * j2], pa, r);
                mma16816(O[2 * j2 + 1], pa, r + 2);
            }
        }
        __syncthreads();
    }

    float inv0 = 1.f / ls[0], inv1 = 1.f / ls[2];
    int row0 = qt * 128 + w * 16 + g;
    __half* op0 = g_ctx16 + (((size_t)(b * SS + row0)) * NH + h) * DD;
    __half* op1 = g_ctx16 + (((size_t)(b * SS + row0 + 8)) * NH + h) * DD;
    #pragma unroll
    for (int j = 0; j < 16; j++) {
        int col = j * 8 + 2 * c;
        *(__half2*)(op0 + col) = __floats2half2_rn(O[j][0] * inv0, O[j][1] * inv0);
        *(__half2*)(op1 + col) = __floats2half2_rn(O[j][2] * inv1, O[j][3] * inv1);
    }
}

// ---------------- launch ----------------
extern "C" void kernel_launch(void* const* d_in, const int* in_sizes, int n_in,
                              void* d_out, int out_size)
{
    const float* hidden = (const float*)d_in[0];
    const float* lnw    = (const float*)d_in[1];
    const float* Wq     = (const float*)d_in[2];
    const float* bq     = (const float*)d_in[3];
    const float* Wk     = (const float*)d_in[4];
    const float* bk     = (const float*)d_in[5];
    const float* Wv     = (const float*)d_in[6];
    const float* bv     = (const float*)d_in[7];
    const float* Wo     = (const float*)d_in[8];
    const float* cosb   = (const float*)d_in[9];
    const float* sinb   = (const float*)d_in[10];
    const float* kc_in  = (const float*)d_in[11];
    const float* vc_in  = (const float*)d_in[12];
    const int*   pos    = (const int*)d_in[13];

    float* out    = (float*)d_out;
    float* kc_out = out + (size_t)BB * SS * HIDN;
    float* vc_out = kc_out + (size_t)BB * MAXS * NKV * DD;

    __half *ph, *pctx, *pw, *pwo;
    cudaGetSymbolAddress((void**)&ph,   g_h16);
    cudaGetSymbolAddress((void**)&pctx, g_ctx16);
    cudaGetSymbolAddress((void**)&pw,   g_w16);
    cudaGetSymbolAddress((void**)&pwo,  g_wo16);

    const int M = BB * SS;   // 4096

    // 0. weight prep (2 kernels)
    transpose_qkv_kernel<<<dim3(64, 96), 256>>>(Wq, Wk, Wv, pw);
    transpose_wo_kernel<<<dim3(64, 64), 256>>>(Wo, pwo);

    // 1. caches base copy (overwritten rows re-written by QKV epilogue)
    cudaMemcpyAsync(kc_out, kc_in, (size_t)BB * MAXS * NKV * DD * sizeof(float),
                    cudaMemcpyDeviceToDevice);
    cudaMemcpyAsync(vc_out, vc_in, (size_t)BB * MAXS * NKV * DD * sizeof(float),
                    cudaMemcpyDeviceToDevice);

    // 2. RMSNorm -> fp16
    rmsnorm16_kernel<<<M, 256>>>(hidden, lnw, ph);

    // 3. fused QKV GEMM + bias + RoPE + qscale + cache writes
    cudaFuncSetAttribute(h16_gemm_kernel<0>, cudaFuncAttributeMaxDynamicSharedMemorySize, GSMEM);
    h16_gemm_kernel<0><<<dim3(24, 32), 256, GSMEM>>>(
        ph, pw, bq, bk, bv, nullptr, cosb, sinb, pos, kc_out, vc_out, nullptr);

    // 4. attention
    cudaFuncSetAttribute(attn16_kernel, cudaFuncAttributeMaxDynamicSharedMemorySize, ASMEM);
    attn16_kernel<<<512, 256, ASMEM>>>();

    // 5. Wo GEMM + residual
    cudaFuncSetAttribute(h16_gemm_kernel<1>, cudaFuncAttributeMaxDynamicSharedMemorySize, GSMEM);
    h16_gemm_kernel<1><<<dim3(16, 32), 256, GSMEM>>>(
        pctx, pwo, nullptr, nullptr, nullptr, hidden, nullptr, nullptr, nullptr,
        nullptr, nullptr, out);
}